// round 11
// baseline (speedup 1.0000x reference)
#include <cuda_runtime.h>
#include <cuda_bf16.h>
#include <cstdint>
#include <cstring>

#define NB 4
#define CIN 512
#define C8 64
#define NN 4096

// ---------------- scratch (static; no allocs allowed) ----------------
// K = f^T [b][n][c], Q = g^T [b][n][c]  (bf16 hi/lo, K-major rows of 64)
// V = h   [b][c][n]                      (bf16 hi/lo)
__device__ __align__(16) __nv_bfloat16 g_ft_h[NB * NN * C8];
__device__ __align__(16) __nv_bfloat16 g_ft_l[NB * NN * C8];
__device__ __align__(16) __nv_bfloat16 g_gt_h[NB * NN * C8];
__device__ __align__(16) __nv_bfloat16 g_gt_l[NB * NN * C8];
__device__ __align__(16) __nv_bfloat16 g_h_h[NB * C8 * NN];
__device__ __align__(16) __nv_bfloat16 g_h_l[NB * C8 * NN];
__device__ float g_ao[NB * C8 * NN];

// ---------------- helpers ----------------
__device__ __forceinline__ uint32_t smem_u32(const void* p) {
    uint32_t a;
    asm("{ .reg .u64 t; cvta.to.shared.u64 t, %1; cvt.u32.u64 %0, t; }" : "=r"(a) : "l"(p));
    return a;
}

// FFMA-only exp (avoids MUFU EX2 throughput wall)
__device__ __forceinline__ float fast_exp(float x) {
    float t = fmaxf(x * 1.4426950408889634f, -126.0f);
    float fi = floorf(t);
    float r = t - fi;
    float p =       1.5403530e-4f;
    p = fmaf(p, r,  1.3333558e-3f);
    p = fmaf(p, r,  9.6181291e-3f);
    p = fmaf(p, r,  5.5504109e-2f);
    p = fmaf(p, r,  2.4022651e-1f);
    p = fmaf(p, r,  6.9314718e-1f);
    p = fmaf(p, r,  1.0f);
    return __int_as_float(((int)fi + 127) << 23) * p;
}

// sm_80-era ops — legal on EVERY compilation pass.
#define LDSM4(r, a) \
    asm volatile("ldmatrix.sync.aligned.m8n8.x4.shared.b16 {%0,%1,%2,%3},[%4];" \
        : "=r"((r)[0]), "=r"((r)[1]), "=r"((r)[2]), "=r"((r)[3]) : "r"(a))
#define LDSM4T(r, a) \
    asm volatile("ldmatrix.sync.aligned.m8n8.x4.trans.shared.b16 {%0,%1,%2,%3},[%4];" \
        : "=r"((r)[0]), "=r"((r)[1]), "=r"((r)[2]), "=r"((r)[3]) : "r"(a))
#define CP_ASYNC16(dst, src) \
    asm volatile("cp.async.cg.shared.global [%0], [%1], 16;" :: "r"(dst), "l"(src))
#define CP_COMMIT() asm volatile("cp.async.commit_group;" ::: "memory")
#define CP_WAIT0()  asm volatile("cp.async.wait_group 0;" ::: "memory")

__device__ __forceinline__ void mma_bf16(float* d, const uint32_t* a, uint32_t b0, uint32_t b1) {
    asm volatile("mma.sync.aligned.m16n8k16.row.col.f32.bf16.bf16.f32 "
                 "{%0,%1,%2,%3},{%4,%5,%6,%7},{%8,%9},{%0,%1,%2,%3};"
                 : "+f"(d[0]), "+f"(d[1]), "+f"(d[2]), "+f"(d[3])
                 : "r"(a[0]), "r"(a[1]), "r"(a[2]), "r"(a[3]), "r"(b0), "r"(b1));
}

__device__ __forceinline__ uint32_t pack_bf2(float a, float b) {
    __nv_bfloat162 h2 = __floats2bfloat162_rn(a, b);
    uint32_t u; memcpy(&u, &h2, 4); return u;
}

// ---------------------------------------------------------------------------
// Kernel 1: QKV projections on mma.sync (split-bf16). UNCHANGED.
// ---------------------------------------------------------------------------
#define XP 272
#define WP 144
#define QK_XH 0
#define QK_XL 17408
#define QK_WH 34816
#define QK_WL 44032
#define SMEM_QKV 53248

__global__ __launch_bounds__(256) void qkv_kernel(const float* __restrict__ x,
                                                  const float* __restrict__ Wf,
                                                  const float* __restrict__ Wg,
                                                  const float* __restrict__ Wh) {
    extern __shared__ char sm[];
    const uint32_t sb = smem_u32(sm);
    const int tid = threadIdx.x, wid = tid >> 5, lane = tid & 31;
    const int g = lane >> 2, tg = lane & 3;
    const int n0 = blockIdx.x * 128;
    const int b  = blockIdx.y;
    const int w  = blockIdx.z;
    const float* W = (w == 0) ? Wf : (w == 1 ? Wg : Wh);
    const float* xb = x + (size_t)b * CIN * NN;

    const uint32_t at_row = (lane & 7) + ((lane >> 4) & 1) * 8;
    const uint32_t at_cb  = ((lane >> 3) & 1) * 16;
    const uint32_t aX  = sb + QK_XH + at_row * XP + wid * 32 + at_cb;
    const uint32_t aXl = aX + (QK_XL - QK_XH);
    const uint32_t b_row = ((lane >> 4) & 1) * 8 + (lane & 7);
    const uint32_t b_cb  = ((lane >> 3) & 1) * 16;
    const uint32_t aW  = sb + QK_WH + b_row * WP + b_cb;
    const uint32_t aWl = aW + (QK_WL - QK_WH);

    float d[8][4] = {};

    for (int kci = 0; kci < 8; ++kci) {
        const int kc = kci * 64;
        __syncthreads();
        #pragma unroll
        for (int r = 0; r < 8; ++r) {
            int idx = r * 256 + tid;
            int c = idx >> 5, f4 = idx & 31;
            int n = f4 * 4;
            float4 xv = *(const float4*)&xb[(size_t)(kc + c) * NN + n0 + n];
            __nv_bfloat16 h0 = __float2bfloat16_rn(xv.x);
            __nv_bfloat16 h1 = __float2bfloat16_rn(xv.y);
            __nv_bfloat16 h2 = __float2bfloat16_rn(xv.z);
            __nv_bfloat16 h3 = __float2bfloat16_rn(xv.w);
            uint32_t hA = ((uint32_t)*(uint16_t*)&h1 << 16) | *(uint16_t*)&h0;
            uint32_t hB = ((uint32_t)*(uint16_t*)&h3 << 16) | *(uint16_t*)&h2;
            uint32_t lA = pack_bf2(xv.x - __bfloat162float(h0), xv.y - __bfloat162float(h1));
            uint32_t lB = pack_bf2(xv.z - __bfloat162float(h2), xv.w - __bfloat162float(h3));
            *(uint2*)(sm + QK_XH + c * XP + n * 2) = make_uint2(hA, hB);
            *(uint2*)(sm + QK_XL + c * XP + n * 2) = make_uint2(lA, lB);
        }
        #pragma unroll
        for (int r = 0; r < 4; ++r) {
            int idx = r * 256 + tid;
            int o = idx >> 4, f4 = idx & 15;
            int c = f4 * 4;
            float4 wv = *(const float4*)&W[(size_t)o * CIN + kc + c];
            __nv_bfloat16 h0 = __float2bfloat16_rn(wv.x);
            __nv_bfloat16 h1 = __float2bfloat16_rn(wv.y);
            __nv_bfloat16 h2 = __float2bfloat16_rn(wv.z);
            __nv_bfloat16 h3 = __float2bfloat16_rn(wv.w);
            uint32_t hA = ((uint32_t)*(uint16_t*)&h1 << 16) | *(uint16_t*)&h0;
            uint32_t hB = ((uint32_t)*(uint16_t*)&h3 << 16) | *(uint16_t*)&h2;
            uint32_t lA = pack_bf2(wv.x - __bfloat162float(h0), wv.y - __bfloat162float(h1));
            uint32_t lB = pack_bf2(wv.z - __bfloat162float(h2), wv.w - __bfloat162float(h3));
            *(uint2*)(sm + QK_WH + o * WP + c * 2) = make_uint2(hA, hB);
            *(uint2*)(sm + QK_WL + o * WP + c * 2) = make_uint2(lA, lB);
        }
        __syncthreads();

        #pragma unroll
        for (int kt = 0; kt < 4; ++kt) {
            uint32_t ah[4], al[4];
            LDSM4T(ah, aX + kt * 16 * XP);
            LDSM4T(al, aXl + kt * 16 * XP);
            #pragma unroll
            for (int p = 0; p < 4; ++p) {
                uint32_t bh[4], bl[4];
                LDSM4(bh, aW + p * 16 * WP + kt * 32);
                LDSM4(bl, aWl + p * 16 * WP + kt * 32);
                mma_bf16(d[2 * p],     ah, bh[0], bh[1]);
                mma_bf16(d[2 * p + 1], ah, bh[2], bh[3]);
                mma_bf16(d[2 * p],     ah, bl[0], bl[1]);
                mma_bf16(d[2 * p + 1], ah, bl[2], bl[3]);
                mma_bf16(d[2 * p],     al, bh[0], bh[1]);
                mma_bf16(d[2 * p + 1], al, bh[2], bh[3]);
            }
        }
    }

    if (w < 2) {
        __nv_bfloat16* dh = (w == 0) ? g_ft_h : g_gt_h;
        __nv_bfloat16* dl = (w == 0) ? g_ft_l : g_gt_l;
        #pragma unroll
        for (int ot = 0; ot < 8; ++ot) {
            int o = ot * 8 + 2 * tg;
            int n_a = n0 + wid * 16 + g;
            size_t base_a = ((size_t)b * NN + n_a) * C8 + o;
            size_t base_b = base_a + 8 * C8;
            float v0 = d[ot][0], v1 = d[ot][1], v2 = d[ot][2], v3 = d[ot][3];
            __nv_bfloat16 h0 = __float2bfloat16_rn(v0);
            __nv_bfloat16 h1 = __float2bfloat16_rn(v1);
            __nv_bfloat16 h2 = __float2bfloat16_rn(v2);
            __nv_bfloat16 h3 = __float2bfloat16_rn(v3);
            *(uint32_t*)&dh[base_a] = ((uint32_t)*(uint16_t*)&h1 << 16) | *(uint16_t*)&h0;
            *(uint32_t*)&dh[base_b] = ((uint32_t)*(uint16_t*)&h3 << 16) | *(uint16_t*)&h2;
            *(uint32_t*)&dl[base_a] = pack_bf2(v0 - __bfloat162float(h0), v1 - __bfloat162float(h1));
            *(uint32_t*)&dl[base_b] = pack_bf2(v2 - __bfloat162float(h2), v3 - __bfloat162float(h3));
        }
    } else {
        #pragma unroll
        for (int ot = 0; ot < 8; ++ot) {
            int o = ot * 8 + 2 * tg;
            int n_a = n0 + wid * 16 + g;
            #pragma unroll
            for (int e = 0; e < 2; ++e) {
                #pragma unroll
                for (int rr = 0; rr < 2; ++rr) {
                    float v = d[ot][rr * 2 + e];
                    size_t idx = ((size_t)b * C8 + o + e) * NN + n_a + rr * 8;
                    __nv_bfloat16 h = __float2bfloat16_rn(v);
                    g_h_h[idx] = h;
                    g_h_l[idx] = __float2bfloat16_rn(v - __bfloat162float(h));
                }
            }
        }
    }
}

// ---------------------------------------------------------------------------
// Kernel 2: flash attention, 512 threads / 16 warps (4 per SMSP).
// 128 queries/block (grid 32 x 4 = 128 blocks), 64 key-tiles of 64.
// Warp (wi 0..3, wj 0..3): S[i16][j32], O[c16][j32].
// exp in registers; cp.async double-buffered K/V; 2 syncs/iter.
// ---------------------------------------------------------------------------
#define AQ_PITCH 144
#define AP_PITCH 272
#define AT_QH 0
#define AT_QL 18432
#define AT_KV 36864            // + buf*36864 ; within: KH 0, KL 9216, VH 18432, VL 27648
#define AT_PH 110592
#define AT_PL 128000
#define AT_RED 145408          // [4 wi][128 col] fp32
#define AT_LROW 147456
#define AT_LINV 147968
#define SMEM_ATTN 148480

__global__ __launch_bounds__(512, 1) void attn_kernel() {
    extern __shared__ char sm[];
    const uint32_t sb = smem_u32(sm);
    const int tid = threadIdx.x, wid = tid >> 5, lane = tid & 31;
    const int g = lane >> 2, tg = lane & 3;
    const int wi = wid & 3, wj = wid >> 2;      // wi: 16-i strip, wj: 32-j quarter
    const int j0 = blockIdx.x * 128;
    const int b  = blockIdx.y;
    float* red  = (float*)(sm + AT_RED);
    float* lrow = (float*)(sm + AT_LROW);
    float* linv = (float*)(sm + AT_LINV);

    const uint4* kh_g = (const uint4*)(g_ft_h + (size_t)b * NN * C8);
    const uint4* kl_g = (const uint4*)(g_ft_l + (size_t)b * NN * C8);
    const uint4* vh_g = (const uint4*)(g_h_h + (size_t)b * C8 * NN);
    const uint4* vl_g = (const uint4*)(g_h_l + (size_t)b * C8 * NN);

    // stage Q tile (128 j x 64 c, hi/lo) — resident
    {
        const uint4* qh = (const uint4*)(g_gt_h + ((size_t)b * NN + j0) * C8);
        const uint4* ql = (const uint4*)(g_gt_l + ((size_t)b * NN + j0) * C8);
        #pragma unroll
        for (int r = 0; r < 2; ++r) {
            int u = r * 512 + tid;
            int row = u >> 3, q = u & 7;
            *(uint4*)(sm + AT_QH + row * AQ_PITCH + q * 16) = qh[row * 8 + q];
            *(uint4*)(sm + AT_QL + row * AQ_PITCH + q * 16) = ql[row * 8 + q];
        }
    }
    if (tid < 128) lrow[tid] = 0.0f;

    // ldmatrix lane offsets
    const uint32_t a_row = (lane & 7) + ((lane >> 3) & 1) * 8;
    const uint32_t a_cb  = ((lane >> 4) & 1) * 16;
    const uint32_t offK = (wi * 16 + a_row) * AQ_PITCH + a_cb;            // within KH
    const uint32_t offV = 18432 + (wi * 16 + a_row) * AQ_PITCH + a_cb;    // within buf
    const uint32_t b_row = ((lane >> 4) & 1) * 8 + (lane & 7);
    const uint32_t b_cb  = ((lane >> 3) & 1) * 16;
    uint32_t aQ[2], aQl[2];
    #pragma unroll
    for (int ntp = 0; ntp < 2; ++ntp) {
        aQ[ntp]  = sb + AT_QH + (wj * 32 + ntp * 16 + b_row) * AQ_PITCH + b_cb;
        aQl[ntp] = aQ[ntp] + (AT_QL - AT_QH);
    }
    const uint32_t p_row = ((lane >> 3) & 1) * 8 + (lane & 7);
    const uint32_t p_cb  = ((lane >> 4) & 1) * 16;
    uint32_t aP[2];
    #pragma unroll
    for (int ntp = 0; ntp < 2; ++ntp)
        aP[ntp] = sb + AT_PH + p_row * AP_PITCH + wj * 64 + ntp * 32 + p_cb;

    // cp.async staging of K/V tile for iter `it` into buffer `buf`
    auto stage_kv = [&](int it, int buf) {
        const int i0 = it * 64;
        const uint32_t kvb = sb + AT_KV + buf * 36864;
        int row = tid >> 3, q = tid & 7;
        uint32_t drow = kvb + row * AQ_PITCH + q * 16;
        CP_ASYNC16(drow, kh_g + (size_t)(i0 + row) * 8 + q);
        CP_ASYNC16(drow + 9216, kl_g + (size_t)(i0 + row) * 8 + q);
        size_t vsrc = (size_t)row * (NN / 8) + (i0 >> 3) + q;   // row = c here
        CP_ASYNC16(drow + 18432, vh_g + vsrc);
        CP_ASYNC16(drow + 27648, vl_g + vsrc);
    };

    stage_kv(0, 0);
    CP_COMMIT();

    float o[4][4] = {};

    for (int it = 0; it < 64; ++it) {
        const int buf = it & 1;
        const uint32_t kvb = sb + AT_KV + buf * 36864;
        CP_WAIT0();
        __syncthreads();   // cp.async data visible; prev iter P/red reads done

        // ---- S[i16][j32] = K·Q^T, split-bf16 ----
        float d[4][4] = {};
        const uint32_t aK = kvb + offK, aKl = aK + 9216;
        #pragma unroll
        for (int kt = 0; kt < 4; ++kt) {
            uint32_t ah[4], al[4];
            LDSM4(ah, aK + kt * 32);
            LDSM4(al, aKl + kt * 32);
            #pragma unroll
            for (int ntp = 0; ntp < 2; ++ntp) {
                uint32_t bh[4], bl[4];
                LDSM4(bh, aQ[ntp] + kt * 32);
                LDSM4(bl, aQl[ntp] + kt * 32);
                mma_bf16(d[ntp * 2],     ah, bh[0], bh[1]);
                mma_bf16(d[ntp * 2 + 1], ah, bh[2], bh[3]);
                mma_bf16(d[ntp * 2],     ah, bl[0], bl[1]);
                mma_bf16(d[ntp * 2 + 1], ah, bl[2], bl[3]);
                mma_bf16(d[ntp * 2],     al, bh[0], bh[1]);
                mma_bf16(d[ntp * 2 + 1], al, bh[2], bh[3]);
            }
        }

        // stage next iter's K/V into the other buffer (overlaps exp + PV)
        if (it + 1 < 64) {
            stage_kv(it + 1, buf ^ 1);
            CP_COMMIT();
        }

        // ---- exp in registers -> split-bf16 P smem + column partials ----
        {
            const int r0 = wi * 16 + g;
            #pragma unroll
            for (int nt = 0; nt < 4; ++nt) {
                float e0 = fast_exp(d[nt][0]);
                float e1 = fast_exp(d[nt][1]);
                float e2 = fast_exp(d[nt][2]);
                float e3 = fast_exp(d[nt][3]);
                const int jc = wj * 32 + nt * 8 + 2 * tg;
                __nv_bfloat162 hA = __floats2bfloat162_rn(e0, e1);
                __nv_bfloat162 hB = __floats2bfloat162_rn(e2, e3);
                uint32_t uhA, uhB; memcpy(&uhA, &hA, 4); memcpy(&uhB, &hB, 4);
                *(uint32_t*)(sm + AT_PH + r0 * AP_PITCH + jc * 2) = uhA;
                *(uint32_t*)(sm + AT_PH + (r0 + 8) * AP_PITCH + jc * 2) = uhB;
                *(uint32_t*)(sm + AT_PL + r0 * AP_PITCH + jc * 2) =
                    pack_bf2(e0 - __bfloat162float(hA.x), e1 - __bfloat162float(hA.y));
                *(uint32_t*)(sm + AT_PL + (r0 + 8) * AP_PITCH + jc * 2) =
                    pack_bf2(e2 - __bfloat162float(hB.x), e3 - __bfloat162float(hB.y));
                float p0 = e0 + e2, p1 = e1 + e3;
                p0 += __shfl_down_sync(0xffffffffu, p0, 16);
                p1 += __shfl_down_sync(0xffffffffu, p1, 16);
                p0 += __shfl_down_sync(0xffffffffu, p0, 8);
                p1 += __shfl_down_sync(0xffffffffu, p1, 8);
                p0 += __shfl_down_sync(0xffffffffu, p0, 4);
                p1 += __shfl_down_sync(0xffffffffu, p1, 4);
                if (lane < 4) {
                    int col = wj * 32 + nt * 8 + 2 * lane;
                    red[wi * 128 + col] = p0;
                    red[wi * 128 + col + 1] = p1;
                }
            }
        }
        __syncthreads();   // P + red visible

        if (tid < 128)
            lrow[tid] += red[tid] + red[128 + tid] + red[256 + tid] + red[384 + tid];

        // ---- O[c16][j32] += V·P, split-bf16 ----
        const uint32_t aV = kvb + offV, aVl = aV + 9216;
        #pragma unroll
        for (int kt = 0; kt < 4; ++kt) {
            uint32_t ah[4], al[4];
            LDSM4(ah, aV + kt * 32);
            LDSM4(al, aVl + kt * 32);
            #pragma unroll
            for (int ntp = 0; ntp < 2; ++ntp) {
                uint32_t bh[4], bl[4];
                LDSM4T(bh, aP[ntp] + kt * (16 * AP_PITCH));
                LDSM4T(bl, aP[ntp] + (AT_PL - AT_PH) + kt * (16 * AP_PITCH));
                mma_bf16(o[ntp * 2],     ah, bh[0], bh[1]);
                mma_bf16(o[ntp * 2 + 1], ah, bh[2], bh[3]);
                mma_bf16(o[ntp * 2],     ah, bl[0], bl[1]);
                mma_bf16(o[ntp * 2 + 1], ah, bl[2], bl[3]);
                mma_bf16(o[ntp * 2],     al, bh[0], bh[1]);
                mma_bf16(o[ntp * 2 + 1], al, bh[2], bh[3]);
            }
        }
    }

    __syncthreads();
    if (tid < 128) linv[tid] = 1.0f / lrow[tid];
    __syncthreads();

    float* ao = g_ao + (size_t)b * C8 * NN;
    #pragma unroll
    for (int nt = 0; nt < 4; ++nt) {
        int jc = wj * 32 + nt * 8 + 2 * tg;
        float v0 = linv[jc], v1 = linv[jc + 1];
        int c0 = wi * 16 + g;
        *(float2*)&ao[(size_t)c0 * NN + j0 + jc] =
            make_float2(o[nt][0] * v0, o[nt][1] * v1);
        *(float2*)&ao[(size_t)(c0 + 8) * NN + j0 + jc] =
            make_float2(o[nt][2] * v0, o[nt][3] * v1);
    }
}

// ---------------------------------------------------------------------------
// Kernel 3: sa = Wv @ AO ; out = sa*gamma + x ; write both outputs.
// ---------------------------------------------------------------------------
__global__ void proj_kernel(const float* __restrict__ x,
                            const float* __restrict__ Wv,
                            const float* __restrict__ gammap,
                            float* __restrict__ out) {
    __shared__ float Wvs[64 * 65];
    __shared__ float As[64 * 64];
    const int n0 = blockIdx.x * 64;
    const int m0 = blockIdx.y * 64;
    const int b  = blockIdx.z;
    const int tid = threadIdx.x;
    const int mg = tid >> 4, ng = tid & 15;

    {
        int idx = tid;
        #pragma unroll
        for (int r = 0; r < 16; ++r) {
            int m = idx >> 6, k = idx & 63;
            Wvs[m * 65 + k] = Wv[(size_t)(m0 + m) * C8 + k];
            idx += 256;
        }
    }
    {
        const float* A = g_ao + (size_t)b * C8 * NN;
        int idx = tid;
        #pragma unroll
        for (int r = 0; r < 16; ++r) {
            int k = idx >> 6, n = idx & 63;
            As[k * 64 + n] = A[(size_t)k * NN + n0 + n];
            idx += 256;
        }
    }
    __syncthreads();

    float acc[4][4] = {};
    #pragma unroll 8
    for (int k = 0; k < 64; ++k) {
        float a0 = Wvs[(mg * 4 + 0) * 65 + k];
        float a1 = Wvs[(mg * 4 + 1) * 65 + k];
        float a2 = Wvs[(mg * 4 + 2) * 65 + k];
        float a3 = Wvs[(mg * 4 + 3) * 65 + k];
        float4 bv = *(const float4*)&As[k * 64 + ng * 4];
        acc[0][0] = fmaf(a0, bv.x, acc[0][0]); acc[0][1] = fmaf(a0, bv.y, acc[0][1]);
        acc[0][2] = fmaf(a0, bv.z, acc[0][2]); acc[0][3] = fmaf(a0, bv.w, acc[0][3]);
        acc[1][0] = fmaf(a1, bv.x, acc[1][0]); acc[1][1] = fmaf(a1, bv.y, acc[1][1]);
        acc[1][2] = fmaf(a1, bv.z, acc[1][2]); acc[1][3] = fmaf(a1, bv.w, acc[1][3]);
        acc[2][0] = fmaf(a2, bv.x, acc[2][0]); acc[2][1] = fmaf(a2, bv.y, acc[2][1]);
        acc[2][2] = fmaf(a2, bv.z, acc[2][2]); acc[2][3] = fmaf(a2, bv.w, acc[2][3]);
        acc[3][0] = fmaf(a3, bv.x, acc[3][0]); acc[3][1] = fmaf(a3, bv.y, acc[3][1]);
        acc[3][2] = fmaf(a3, bv.z, acc[3][2]); acc[3][3] = fmaf(a3, bv.w, acc[3][3]);
    }

    const float gamma = gammap[0];
    float* outSA = out + (size_t)NB * CIN * NN;
    #pragma unroll
    for (int dm = 0; dm < 4; ++dm) {
        int m = m0 + mg * 4 + dm;
        size_t base = ((size_t)b * CIN + m) * NN + n0 + ng * 4;
        float4 sa = make_float4(acc[dm][0], acc[dm][1], acc[dm][2], acc[dm][3]);
        *(float4*)&outSA[base] = sa;
        float4 xv = *(const float4*)&x[base];
        float4 ov = make_float4(fmaf(sa.x, gamma, xv.x), fmaf(sa.y, gamma, xv.y),
                                fmaf(sa.z, gamma, xv.z), fmaf(sa.w, gamma, xv.w));
        *(float4*)&out[base] = ov;
    }
}

extern "C" void kernel_launch(void* const* d_in, const int* in_sizes, int n_in,
                              void* d_out, int out_size) {
    const float* x     = (const float*)d_in[0];
    const float* Wf    = (const float*)d_in[1];
    const float* Wg    = (const float*)d_in[2];
    const float* Wh    = (const float*)d_in[3];
    const float* Wv    = (const float*)d_in[4];
    const float* gamma = (const float*)d_in[5];
    float* out = (float*)d_out;

    cudaFuncSetAttribute(qkv_kernel,
                         cudaFuncAttributeMaxDynamicSharedMemorySize, SMEM_QKV);
    cudaFuncSetAttribute(attn_kernel,
                         cudaFuncAttributeMaxDynamicSharedMemorySize, SMEM_ATTN);

    qkv_kernel<<<dim3(32, 4, 3), 256, SMEM_QKV>>>(x, Wf, Wg, Wh);
    attn_kernel<<<dim3(32, 4), 512, SMEM_ATTN>>>();
    proj_kernel<<<dim3(64, 8, 4), 256>>>(x, Wv, gamma, out);
}

// round 12
// speedup vs baseline: 1.1552x; 1.1552x over previous
#include <cuda_runtime.h>
#include <cuda_bf16.h>
#include <cstdint>
#include <cstring>

#define NB 4
#define CIN 512
#define C8 64
#define NN 4096

// ---------------- scratch (static; no allocs allowed) ----------------
__device__ __align__(16) __nv_bfloat16 g_ft_h[NB * NN * C8];
__device__ __align__(16) __nv_bfloat16 g_ft_l[NB * NN * C8];
__device__ __align__(16) __nv_bfloat16 g_gt_h[NB * NN * C8];
__device__ __align__(16) __nv_bfloat16 g_gt_l[NB * NN * C8];
__device__ __align__(16) __nv_bfloat16 g_h_h[NB * C8 * NN];
__device__ __align__(16) __nv_bfloat16 g_h_l[NB * C8 * NN];
__device__ float g_ao[NB * C8 * NN];

// ---------------- helpers ----------------
__device__ __forceinline__ uint32_t smem_u32(const void* p) {
    uint32_t a;
    asm("{ .reg .u64 t; cvta.to.shared.u64 t, %1; cvt.u32.u64 %0, t; }" : "=r"(a) : "l"(p));
    return a;
}

__device__ __forceinline__ float fast_exp(float x) {
    float t = fmaxf(x * 1.4426950408889634f, -126.0f);
    float fi = floorf(t);
    float r = t - fi;
    float p =       1.5403530e-4f;
    p = fmaf(p, r,  1.3333558e-3f);
    p = fmaf(p, r,  9.6181291e-3f);
    p = fmaf(p, r,  5.5504109e-2f);
    p = fmaf(p, r,  2.4022651e-1f);
    p = fmaf(p, r,  6.9314718e-1f);
    p = fmaf(p, r,  1.0f);
    return __int_as_float(((int)fi + 127) << 23) * p;
}

// sm_75/80-era ops — legal on EVERY compilation pass.
#define LDSM4(r, a) \
    asm volatile("ldmatrix.sync.aligned.m8n8.x4.shared.b16 {%0,%1,%2,%3},[%4];" \
        : "=r"((r)[0]), "=r"((r)[1]), "=r"((r)[2]), "=r"((r)[3]) : "r"(a))
#define LDSM4T(r, a) \
    asm volatile("ldmatrix.sync.aligned.m8n8.x4.trans.shared.b16 {%0,%1,%2,%3},[%4];" \
        : "=r"((r)[0]), "=r"((r)[1]), "=r"((r)[2]), "=r"((r)[3]) : "r"(a))
#define MOVMAT(d, s) \
    asm volatile("movmatrix.sync.aligned.m8n8.trans.b16 %0, %1;" : "=r"(d) : "r"(s))
#define CP_ASYNC16(dst, src) \
    asm volatile("cp.async.cg.shared.global [%0], [%1], 16;" :: "r"(dst), "l"(src))
#define CP_COMMIT() asm volatile("cp.async.commit_group;" ::: "memory")
#define CP_WAIT0()  asm volatile("cp.async.wait_group 0;" ::: "memory")

__device__ __forceinline__ void mma_bf16(float* d, const uint32_t* a, uint32_t b0, uint32_t b1) {
    asm volatile("mma.sync.aligned.m16n8k16.row.col.f32.bf16.bf16.f32 "
                 "{%0,%1,%2,%3},{%4,%5,%6,%7},{%8,%9},{%0,%1,%2,%3};"
                 : "+f"(d[0]), "+f"(d[1]), "+f"(d[2]), "+f"(d[3])
                 : "r"(a[0]), "r"(a[1]), "r"(a[2]), "r"(a[3]), "r"(b0), "r"(b1));
}

__device__ __forceinline__ uint32_t pack_bf2(float a, float b) {
    __nv_bfloat162 h2 = __floats2bfloat162_rn(a, b);
    uint32_t u; memcpy(&u, &h2, 4); return u;
}

// ---------------------------------------------------------------------------
// Kernel 1: QKV projections on mma.sync (split-bf16). UNCHANGED (55.6us).
// ---------------------------------------------------------------------------
#define XP 272
#define WP 144
#define QK_XH 0
#define QK_XL 17408
#define QK_WH 34816
#define QK_WL 44032
#define SMEM_QKV 53248

__global__ __launch_bounds__(256) void qkv_kernel(const float* __restrict__ x,
                                                  const float* __restrict__ Wf,
                                                  const float* __restrict__ Wg,
                                                  const float* __restrict__ Wh) {
    extern __shared__ char sm[];
    const uint32_t sb = smem_u32(sm);
    const int tid = threadIdx.x, wid = tid >> 5, lane = tid & 31;
    const int g = lane >> 2, tg = lane & 3;
    const int n0 = blockIdx.x * 128;
    const int b  = blockIdx.y;
    const int w  = blockIdx.z;
    const float* W = (w == 0) ? Wf : (w == 1 ? Wg : Wh);
    const float* xb = x + (size_t)b * CIN * NN;

    const uint32_t at_row = (lane & 7) + ((lane >> 4) & 1) * 8;
    const uint32_t at_cb  = ((lane >> 3) & 1) * 16;
    const uint32_t aX  = sb + QK_XH + at_row * XP + wid * 32 + at_cb;
    const uint32_t aXl = aX + (QK_XL - QK_XH);
    const uint32_t b_row = ((lane >> 4) & 1) * 8 + (lane & 7);
    const uint32_t b_cb  = ((lane >> 3) & 1) * 16;
    const uint32_t aW  = sb + QK_WH + b_row * WP + b_cb;
    const uint32_t aWl = aW + (QK_WL - QK_WH);

    float d[8][4] = {};

    for (int kci = 0; kci < 8; ++kci) {
        const int kc = kci * 64;
        __syncthreads();
        #pragma unroll
        for (int r = 0; r < 8; ++r) {
            int idx = r * 256 + tid;
            int c = idx >> 5, f4 = idx & 31;
            int n = f4 * 4;
            float4 xv = *(const float4*)&xb[(size_t)(kc + c) * NN + n0 + n];
            __nv_bfloat16 h0 = __float2bfloat16_rn(xv.x);
            __nv_bfloat16 h1 = __float2bfloat16_rn(xv.y);
            __nv_bfloat16 h2 = __float2bfloat16_rn(xv.z);
            __nv_bfloat16 h3 = __float2bfloat16_rn(xv.w);
            uint32_t hA = ((uint32_t)*(uint16_t*)&h1 << 16) | *(uint16_t*)&h0;
            uint32_t hB = ((uint32_t)*(uint16_t*)&h3 << 16) | *(uint16_t*)&h2;
            uint32_t lA = pack_bf2(xv.x - __bfloat162float(h0), xv.y - __bfloat162float(h1));
            uint32_t lB = pack_bf2(xv.z - __bfloat162float(h2), xv.w - __bfloat162float(h3));
            *(uint2*)(sm + QK_XH + c * XP + n * 2) = make_uint2(hA, hB);
            *(uint2*)(sm + QK_XL + c * XP + n * 2) = make_uint2(lA, lB);
        }
        #pragma unroll
        for (int r = 0; r < 4; ++r) {
            int idx = r * 256 + tid;
            int o = idx >> 4, f4 = idx & 15;
            int c = f4 * 4;
            float4 wv = *(const float4*)&W[(size_t)o * CIN + kc + c];
            __nv_bfloat16 h0 = __float2bfloat16_rn(wv.x);
            __nv_bfloat16 h1 = __float2bfloat16_rn(wv.y);
            __nv_bfloat16 h2 = __float2bfloat16_rn(wv.z);
            __nv_bfloat16 h3 = __float2bfloat16_rn(wv.w);
            uint32_t hA = ((uint32_t)*(uint16_t*)&h1 << 16) | *(uint16_t*)&h0;
            uint32_t hB = ((uint32_t)*(uint16_t*)&h3 << 16) | *(uint16_t*)&h2;
            uint32_t lA = pack_bf2(wv.x - __bfloat162float(h0), wv.y - __bfloat162float(h1));
            uint32_t lB = pack_bf2(wv.z - __bfloat162float(h2), wv.w - __bfloat162float(h3));
            *(uint2*)(sm + QK_WH + o * WP + c * 2) = make_uint2(hA, hB);
            *(uint2*)(sm + QK_WL + o * WP + c * 2) = make_uint2(lA, lB);
        }
        __syncthreads();

        #pragma unroll
        for (int kt = 0; kt < 4; ++kt) {
            uint32_t ah[4], al[4];
            LDSM4T(ah, aX + kt * 16 * XP);
            LDSM4T(al, aXl + kt * 16 * XP);
            #pragma unroll
            for (int p = 0; p < 4; ++p) {
                uint32_t bh[4], bl[4];
                LDSM4(bh, aW + p * 16 * WP + kt * 32);
                LDSM4(bl, aWl + p * 16 * WP + kt * 32);
                mma_bf16(d[2 * p],     ah, bh[0], bh[1]);
                mma_bf16(d[2 * p + 1], ah, bh[2], bh[3]);
                mma_bf16(d[2 * p],     ah, bl[0], bl[1]);
                mma_bf16(d[2 * p + 1], ah, bl[2], bl[3]);
                mma_bf16(d[2 * p],     al, bh[0], bh[1]);
                mma_bf16(d[2 * p + 1], al, bh[2], bh[3]);
            }
        }
    }

    if (w < 2) {
        __nv_bfloat16* dh = (w == 0) ? g_ft_h : g_gt_h;
        __nv_bfloat16* dl = (w == 0) ? g_ft_l : g_gt_l;
        #pragma unroll
        for (int ot = 0; ot < 8; ++ot) {
            int o = ot * 8 + 2 * tg;
            int n_a = n0 + wid * 16 + g;
            size_t base_a = ((size_t)b * NN + n_a) * C8 + o;
            size_t base_b = base_a + 8 * C8;
            float v0 = d[ot][0], v1 = d[ot][1], v2 = d[ot][2], v3 = d[ot][3];
            __nv_bfloat16 h0 = __float2bfloat16_rn(v0);
            __nv_bfloat16 h1 = __float2bfloat16_rn(v1);
            __nv_bfloat16 h2 = __float2bfloat16_rn(v2);
            __nv_bfloat16 h3 = __float2bfloat16_rn(v3);
            *(uint32_t*)&dh[base_a] = ((uint32_t)*(uint16_t*)&h1 << 16) | *(uint16_t*)&h0;
            *(uint32_t*)&dh[base_b] = ((uint32_t)*(uint16_t*)&h3 << 16) | *(uint16_t*)&h2;
            *(uint32_t*)&dl[base_a] = pack_bf2(v0 - __bfloat162float(h0), v1 - __bfloat162float(h1));
            *(uint32_t*)&dl[base_b] = pack_bf2(v2 - __bfloat162float(h2), v3 - __bfloat162float(h3));
        }
    } else {
        #pragma unroll
        for (int ot = 0; ot < 8; ++ot) {
            int o = ot * 8 + 2 * tg;
            int n_a = n0 + wid * 16 + g;
            #pragma unroll
            for (int e = 0; e < 2; ++e) {
                #pragma unroll
                for (int rr = 0; rr < 2; ++rr) {
                    float v = d[ot][rr * 2 + e];
                    size_t idx = ((size_t)b * C8 + o + e) * NN + n_a + rr * 8;
                    __nv_bfloat16 h = __float2bfloat16_rn(v);
                    g_h_h[idx] = h;
                    g_h_l[idx] = __float2bfloat16_rn(v - __bfloat162float(h));
                }
            }
        }
    }
}

// ---------------------------------------------------------------------------
// Kernel 2: flash attention — P stays in registers (movmatrix transpose).
// 512 threads / 16 warps. Warp (wi<4, wj<4): S(i16 strip, j32) -> exp in regs
// -> movmatrix -> PV over own strip: O_partial(c64, j32). wi-partials reduced
// through smem ONCE after the loop. Column sums in registers across iters.
// One __syncthreads per iteration.
// ---------------------------------------------------------------------------
#define AQ_PITCH 144
#define AT_QH 0
#define AT_QL 18432
#define AT_KV 36864            // + buf*36864 ; KH 0, KL 9216, VH 18432, VL 27648
#define AT_OSM 0               // after loop: [4 wi][64 c][128 j] fp32 (128 KB)
#define AT_RED 131072          // [4 wi][128 j]
#define AT_LINV 133120
#define SMEM_ATTN 133632

__global__ __launch_bounds__(512, 1) void attn_kernel() {
    extern __shared__ char sm[];
    const uint32_t sb = smem_u32(sm);
    const int tid = threadIdx.x, wid = tid >> 5, lane = tid & 31;
    const int g = lane >> 2, tg = lane & 3;
    const int wi = wid & 3, wj = wid >> 2;
    const int j0 = blockIdx.x * 128;
    const int b  = blockIdx.y;

    const uint4* kh_g = (const uint4*)(g_ft_h + (size_t)b * NN * C8);
    const uint4* kl_g = (const uint4*)(g_ft_l + (size_t)b * NN * C8);
    const uint4* vh_g = (const uint4*)(g_h_h + (size_t)b * C8 * NN);
    const uint4* vl_g = (const uint4*)(g_h_l + (size_t)b * C8 * NN);

    {   // stage Q tile (128 j x 64 c, hi/lo) — resident for whole loop
        const uint4* qh = (const uint4*)(g_gt_h + ((size_t)b * NN + j0) * C8);
        const uint4* ql = (const uint4*)(g_gt_l + ((size_t)b * NN + j0) * C8);
        #pragma unroll
        for (int r = 0; r < 2; ++r) {
            int u = r * 512 + tid;
            int row = u >> 3, q = u & 7;
            *(uint4*)(sm + AT_QH + row * AQ_PITCH + q * 16) = qh[row * 8 + q];
            *(uint4*)(sm + AT_QL + row * AQ_PITCH + q * 16) = ql[row * 8 + q];
        }
    }

    // lane offsets
    const uint32_t offK = (wi * 16 + (lane & 15)) * AQ_PITCH + ((lane >> 4) & 1) * 16;
    const uint32_t offV0 = 18432 + (lane & 15) * AQ_PITCH + wi * 32 + ((lane >> 4) & 1) * 16;
    const uint32_t b_row = ((lane >> 4) & 1) * 8 + (lane & 7);
    const uint32_t b_cb  = ((lane >> 3) & 1) * 16;
    uint32_t aQ[2], aQl[2];
    #pragma unroll
    for (int ntp = 0; ntp < 2; ++ntp) {
        aQ[ntp]  = sb + AT_QH + (wj * 32 + ntp * 16 + b_row) * AQ_PITCH + b_cb;
        aQl[ntp] = aQ[ntp] + (AT_QL - AT_QH);
    }

    auto stage_kv = [&](int it, int buf) {
        const int i0 = it * 64;
        const uint32_t kvb = sb + AT_KV + buf * 36864;
        int row = tid >> 3, q = tid & 7;
        uint32_t drow = kvb + row * AQ_PITCH + q * 16;
        CP_ASYNC16(drow, kh_g + (size_t)(i0 + row) * 8 + q);
        CP_ASYNC16(drow + 9216, kl_g + (size_t)(i0 + row) * 8 + q);
        size_t vsrc = (size_t)row * (NN / 8) + (i0 >> 3) + q;   // row = c
        CP_ASYNC16(drow + 18432, vh_g + vsrc);
        CP_ASYNC16(drow + 27648, vl_g + vsrc);
    };

    stage_kv(0, 0);
    CP_COMMIT();

    float o[16][4] = {};     // [ct*4+nt]: O_partial(c = ct*16.., j = wj*32+nt*8..)
    float ls[8] = {};        // column-sum partials [nt][e]

    for (int it = 0; it < 64; ++it) {
        const int buf = it & 1;
        const uint32_t kvb = sb + AT_KV + buf * 36864;
        CP_WAIT0();
        __syncthreads();   // K/V tile ready; prior reads of buf^1 complete

        // ---- S(i16, j32) = K·Q^T, split-bf16 ----
        float d[4][4] = {};
        const uint32_t aK = kvb + offK, aKl = aK + 9216;
        #pragma unroll
        for (int kt = 0; kt < 4; ++kt) {
            uint32_t ah[4], al[4];
            LDSM4(ah, aK + kt * 32);
            LDSM4(al, aKl + kt * 32);
            #pragma unroll
            for (int ntp = 0; ntp < 2; ++ntp) {
                uint32_t bh[4], bl[4];
                LDSM4(bh, aQ[ntp] + kt * 32);
                LDSM4(bl, aQl[ntp] + kt * 32);
                mma_bf16(d[ntp * 2],     ah, bh[0], bh[1]);
                mma_bf16(d[ntp * 2 + 1], ah, bh[2], bh[3]);
                mma_bf16(d[ntp * 2],     ah, bl[0], bl[1]);
                mma_bf16(d[ntp * 2 + 1], ah, bl[2], bl[3]);
                mma_bf16(d[ntp * 2],     al, bh[0], bh[1]);
                mma_bf16(d[ntp * 2 + 1], al, bh[2], bh[3]);
            }
        }

        // stage next tile (overlaps exp + PV)
        if (it + 1 < 64) {
            stage_kv(it + 1, buf ^ 1);
            CP_COMMIT();
        }

        // ---- exp in regs -> pack -> movmatrix: P as B-fragments ----
        uint32_t pb[4][4];   // [nt]{b0h, b1h, b0l, b1l}
        #pragma unroll
        for (int nt = 0; nt < 4; ++nt) {
            float e0 = fast_exp(d[nt][0]);
            float e1 = fast_exp(d[nt][1]);
            float e2 = fast_exp(d[nt][2]);
            float e3 = fast_exp(d[nt][3]);
            ls[nt * 2]     += e0 + e2;
            ls[nt * 2 + 1] += e1 + e3;
            __nv_bfloat162 hA = __floats2bfloat162_rn(e0, e1);
            __nv_bfloat162 hB = __floats2bfloat162_rn(e2, e3);
            uint32_t uhA, uhB; memcpy(&uhA, &hA, 4); memcpy(&uhB, &hB, 4);
            uint32_t ulA = pack_bf2(e0 - __bfloat162float(hA.x), e1 - __bfloat162float(hA.y));
            uint32_t ulB = pack_bf2(e2 - __bfloat162float(hB.x), e3 - __bfloat162float(hB.y));
            MOVMAT(pb[nt][0], uhA);
            MOVMAT(pb[nt][1], uhB);
            MOVMAT(pb[nt][2], ulA);
            MOVMAT(pb[nt][3], ulB);
        }

        // ---- O_partial(c64, j32) += V(strip)·P, split-bf16 ----
        #pragma unroll
        for (int ct = 0; ct < 4; ++ct) {
            uint32_t vh[4], vl[4];
            uint32_t aV = kvb + offV0 + ct * (16 * AQ_PITCH);
            LDSM4(vh, aV);
            LDSM4(vl, aV + 9216);
            #pragma unroll
            for (int nt = 0; nt < 4; ++nt) {
                float* oo = o[ct * 4 + nt];
                mma_bf16(oo, vh, pb[nt][0], pb[nt][1]);
                mma_bf16(oo, vh, pb[nt][2], pb[nt][3]);
                mma_bf16(oo, vl, pb[nt][0], pb[nt][1]);
            }
        }
    }

    __syncthreads();   // loop done; Q/KV smem regions now dead

    // ---- write O partials: Osm[wi][c][j] ----
    float* Osm = (float*)(sm + AT_OSM);
    #pragma unroll
    for (int ct = 0; ct < 4; ++ct) {
        #pragma unroll
        for (int nt = 0; nt < 4; ++nt) {
            int c = ct * 16 + g;
            int jc = wj * 32 + nt * 8 + 2 * tg;
            float* os = Osm + ((size_t)wi * 64 + c) * 128 + jc;
            os[0] = o[ct * 4 + nt][0];
            os[1] = o[ct * 4 + nt][1];
            os[8 * 128] = o[ct * 4 + nt][2];
            os[8 * 128 + 1] = o[ct * 4 + nt][3];
        }
    }
    // ---- column-sum reduction (over g lanes, then wi via smem) ----
    float* red = (float*)(sm + AT_RED);
    #pragma unroll
    for (int nt = 0; nt < 4; ++nt) {
        #pragma unroll
        for (int e = 0; e < 2; ++e) {
            float v = ls[nt * 2 + e];
            v += __shfl_down_sync(0xffffffffu, v, 4);
            v += __shfl_down_sync(0xffffffffu, v, 8);
            v += __shfl_down_sync(0xffffffffu, v, 16);
            if (lane < 4)
                red[wi * 128 + wj * 32 + nt * 8 + 2 * lane + e] = v;
        }
    }
    __syncthreads();

    float* linv = (float*)(sm + AT_LINV);
    if (tid < 128)
        linv[tid] = 1.0f / (red[tid] + red[128 + tid] + red[256 + tid] + red[384 + tid]);
    __syncthreads();

    // ---- final: sum 4 wi-partials, divide, store ----
    {
        const int j = tid & 127;
        const int cg = tid >> 7;          // 0..3
        float inv = linv[j];
        float* ao = g_ao + (size_t)b * C8 * NN + j0 + j;
        #pragma unroll
        for (int k = 0; k < 16; ++k) {
            int c = cg * 16 + k;
            float v = Osm[(size_t)c * 128 + j]
                    + Osm[(size_t)(64 + c) * 128 + j]
                    + Osm[(size_t)(128 + c) * 128 + j]
                    + Osm[(size_t)(192 + c) * 128 + j];
            ao[(size_t)c * NN] = v * inv;
        }
    }
}

// ---------------------------------------------------------------------------
// Kernel 3: sa = Wv @ AO ; out = sa*gamma + x. UNCHANGED.
// ---------------------------------------------------------------------------
__global__ void proj_kernel(const float* __restrict__ x,
                            const float* __restrict__ Wv,
                            const float* __restrict__ gammap,
                            float* __restrict__ out) {
    __shared__ float Wvs[64 * 65];
    __shared__ float As[64 * 64];
    const int n0 = blockIdx.x * 64;
    const int m0 = blockIdx.y * 64;
    const int b  = blockIdx.z;
    const int tid = threadIdx.x;
    const int mg = tid >> 4, ng = tid & 15;

    {
        int idx = tid;
        #pragma unroll
        for (int r = 0; r < 16; ++r) {
            int m = idx >> 6, k = idx & 63;
            Wvs[m * 65 + k] = Wv[(size_t)(m0 + m) * C8 + k];
            idx += 256;
        }
    }
    {
        const float* A = g_ao + (size_t)b * C8 * NN;
        int idx = tid;
        #pragma unroll
        for (int r = 0; r < 16; ++r) {
            int k = idx >> 6, n = idx & 63;
            As[k * 64 + n] = A[(size_t)k * NN + n0 + n];
            idx += 256;
        }
    }
    __syncthreads();

    float acc[4][4] = {};
    #pragma unroll 8
    for (int k = 0; k < 64; ++k) {
        float a0 = Wvs[(mg * 4 + 0) * 65 + k];
        float a1 = Wvs[(mg * 4 + 1) * 65 + k];
        float a2 = Wvs[(mg * 4 + 2) * 65 + k];
        float a3 = Wvs[(mg * 4 + 3) * 65 + k];
        float4 bv = *(const float4*)&As[k * 64 + ng * 4];
        acc[0][0] = fmaf(a0, bv.x, acc[0][0]); acc[0][1] = fmaf(a0, bv.y, acc[0][1]);
        acc[0][2] = fmaf(a0, bv.z, acc[0][2]); acc[0][3] = fmaf(a0, bv.w, acc[0][3]);
        acc[1][0] = fmaf(a1, bv.x, acc[1][0]); acc[1][1] = fmaf(a1, bv.y, acc[1][1]);
        acc[1][2] = fmaf(a1, bv.z, acc[1][2]); acc[1][3] = fmaf(a1, bv.w, acc[1][3]);
        acc[2][0] = fmaf(a2, bv.x, acc[2][0]); acc[2][1] = fmaf(a2, bv.y, acc[2][1]);
        acc[2][2] = fmaf(a2, bv.z, acc[2][2]); acc[2][3] = fmaf(a2, bv.w, acc[2][3]);
        acc[3][0] = fmaf(a3, bv.x, acc[3][0]); acc[3][1] = fmaf(a3, bv.y, acc[3][1]);
        acc[3][2] = fmaf(a3, bv.z, acc[3][2]); acc[3][3] = fmaf(a3, bv.w, acc[3][3]);
    }

    const float gamma = gammap[0];
    float* outSA = out + (size_t)NB * CIN * NN;
    #pragma unroll
    for (int dm = 0; dm < 4; ++dm) {
        int m = m0 + mg * 4 + dm;
        size_t base = ((size_t)b * CIN + m) * NN + n0 + ng * 4;
        float4 sa = make_float4(acc[dm][0], acc[dm][1], acc[dm][2], acc[dm][3]);
        *(float4*)&outSA[base] = sa;
        float4 xv = *(const float4*)&x[base];
        float4 ov = make_float4(fmaf(sa.x, gamma, xv.x), fmaf(sa.y, gamma, xv.y),
                                fmaf(sa.z, gamma, xv.z), fmaf(sa.w, gamma, xv.w));
        *(float4*)&out[base] = ov;
    }
}

extern "C" void kernel_launch(void* const* d_in, const int* in_sizes, int n_in,
                              void* d_out, int out_size) {
    const float* x     = (const float*)d_in[0];
    const float* Wf    = (const float*)d_in[1];
    const float* Wg    = (const float*)d_in[2];
    const float* Wh    = (const float*)d_in[3];
    const float* Wv    = (const float*)d_in[4];
    const float* gamma = (const float*)d_in[5];
    float* out = (float*)d_out;

    cudaFuncSetAttribute(qkv_kernel,
                         cudaFuncAttributeMaxDynamicSharedMemorySize, SMEM_QKV);
    cudaFuncSetAttribute(attn_kernel,
                         cudaFuncAttributeMaxDynamicSharedMemorySize, SMEM_ATTN);

    qkv_kernel<<<dim3(32, 4, 3), 256, SMEM_QKV>>>(x, Wf, Wg, Wh);
    attn_kernel<<<dim3(32, 4), 512, SMEM_ATTN>>>();
    proj_kernel<<<dim3(64, 8, 4), 256>>>(x, Wv, gamma, out);
}

// round 13
// speedup vs baseline: 1.2401x; 1.0734x over previous
#include <cuda_runtime.h>
#include <cuda_bf16.h>
#include <cstdint>
#include <cstring>

#define NB 4
#define CIN 512
#define C8 64
#define NN 4096

// ---------------- scratch (static; no allocs allowed) ----------------
__device__ __align__(16) __nv_bfloat16 g_ft_h[NB * NN * C8];
__device__ __align__(16) __nv_bfloat16 g_ft_l[NB * NN * C8];
__device__ __align__(16) __nv_bfloat16 g_gt_h[NB * NN * C8];
__device__ __align__(16) __nv_bfloat16 g_gt_l[NB * NN * C8];
__device__ __align__(16) __nv_bfloat16 g_h_h[NB * C8 * NN];
__device__ __align__(16) __nv_bfloat16 g_h_l[NB * C8 * NN];
__device__ float g_ao[NB * C8 * NN];

// ---------------- helpers ----------------
__device__ __forceinline__ uint32_t smem_u32(const void* p) {
    uint32_t a;
    asm("{ .reg .u64 t; cvta.to.shared.u64 t, %1; cvt.u32.u64 %0, t; }" : "=r"(a) : "l"(p));
    return a;
}

__device__ __forceinline__ float fast_exp(float x) {
    float t = fmaxf(x * 1.4426950408889634f, -126.0f);
    float fi = floorf(t);
    float r = t - fi;
    float p =       1.5403530e-4f;
    p = fmaf(p, r,  1.3333558e-3f);
    p = fmaf(p, r,  9.6181291e-3f);
    p = fmaf(p, r,  5.5504109e-2f);
    p = fmaf(p, r,  2.4022651e-1f);
    p = fmaf(p, r,  6.9314718e-1f);
    p = fmaf(p, r,  1.0f);
    return __int_as_float(((int)fi + 127) << 23) * p;
}

// sm_75/80-era ops — legal on EVERY compilation pass.
#define LDSM4(r, a) \
    asm volatile("ldmatrix.sync.aligned.m8n8.x4.shared.b16 {%0,%1,%2,%3},[%4];" \
        : "=r"((r)[0]), "=r"((r)[1]), "=r"((r)[2]), "=r"((r)[3]) : "r"(a))
#define LDSM4T(r, a) \
    asm volatile("ldmatrix.sync.aligned.m8n8.x4.trans.shared.b16 {%0,%1,%2,%3},[%4];" \
        : "=r"((r)[0]), "=r"((r)[1]), "=r"((r)[2]), "=r"((r)[3]) : "r"(a))
#define MOVMAT(d, s) \
    asm volatile("movmatrix.sync.aligned.m8n8.trans.b16 %0, %1;" : "=r"(d) : "r"(s))
#define CP_ASYNC16(dst, src) \
    asm volatile("cp.async.cg.shared.global [%0], [%1], 16;" :: "r"(dst), "l"(src))
#define CP_COMMIT() asm volatile("cp.async.commit_group;" ::: "memory")
#define CP_WAIT0()  asm volatile("cp.async.wait_group 0;" ::: "memory")

__device__ __forceinline__ void mma_bf16(float* d, const uint32_t* a, uint32_t b0, uint32_t b1) {
    asm volatile("mma.sync.aligned.m16n8k16.row.col.f32.bf16.bf16.f32 "
                 "{%0,%1,%2,%3},{%4,%5,%6,%7},{%8,%9},{%0,%1,%2,%3};"
                 : "+f"(d[0]), "+f"(d[1]), "+f"(d[2]), "+f"(d[3])
                 : "r"(a[0]), "r"(a[1]), "r"(a[2]), "r"(a[3]), "r"(b0), "r"(b1));
}

__device__ __forceinline__ uint32_t pack_bf2(float a, float b) {
    __nv_bfloat162 h2 = __floats2bfloat162_rn(a, b);
    uint32_t u; memcpy(&u, &h2, 4); return u;
}

// ---------------------------------------------------------------------------
// Kernel 1: QKV — all 3 weights in ONE kernel, x staged once per chunk.
// D[n 128][o 64] per weight. Grid (32 n-tiles, 4 b), 256 threads.
// ---------------------------------------------------------------------------
#define XP 272
#define WP 144
#define QK_XH 0
#define QK_XL 17408
#define QK_W  34816          // + w*18432 (WH), +9216 (WL)
#define SMEM_QKV 90112

__global__ __launch_bounds__(256) void qkv_kernel(const float* __restrict__ x,
                                                  const float* __restrict__ Wf,
                                                  const float* __restrict__ Wg,
                                                  const float* __restrict__ Wh) {
    extern __shared__ char sm[];
    const uint32_t sb = smem_u32(sm);
    const int tid = threadIdx.x, wid = tid >> 5, lane = tid & 31;
    const int g = lane >> 2, tg = lane & 3;
    const int n0 = blockIdx.x * 128;
    const int b  = blockIdx.y;
    const float* xb = x + (size_t)b * CIN * NN;
    const float* Wp[3] = { Wf, Wg, Wh };

    const uint32_t at_row = (lane & 7) + ((lane >> 4) & 1) * 8;
    const uint32_t at_cb  = ((lane >> 3) & 1) * 16;
    const uint32_t aX  = sb + QK_XH + at_row * XP + wid * 32 + at_cb;
    const uint32_t aXl = aX + (QK_XL - QK_XH);
    const uint32_t b_row = ((lane >> 4) & 1) * 8 + (lane & 7);
    const uint32_t b_cb  = ((lane >> 3) & 1) * 16;
    const uint32_t aW0 = sb + QK_W + b_row * WP + b_cb;

    float d[3][8][4] = {};

    for (int kci = 0; kci < 8; ++kci) {
        const int kc = kci * 64;
        __syncthreads();
        // stage x chunk [64 c][128 n] -> bf16 hi/lo (ONCE for all 3 weights)
        #pragma unroll
        for (int r = 0; r < 8; ++r) {
            int idx = r * 256 + tid;
            int c = idx >> 5, f4 = idx & 31;
            int n = f4 * 4;
            float4 xv = *(const float4*)&xb[(size_t)(kc + c) * NN + n0 + n];
            __nv_bfloat16 h0 = __float2bfloat16_rn(xv.x);
            __nv_bfloat16 h1 = __float2bfloat16_rn(xv.y);
            __nv_bfloat16 h2 = __float2bfloat16_rn(xv.z);
            __nv_bfloat16 h3 = __float2bfloat16_rn(xv.w);
            uint32_t hA = ((uint32_t)*(uint16_t*)&h1 << 16) | *(uint16_t*)&h0;
            uint32_t hB = ((uint32_t)*(uint16_t*)&h3 << 16) | *(uint16_t*)&h2;
            uint32_t lA = pack_bf2(xv.x - __bfloat162float(h0), xv.y - __bfloat162float(h1));
            uint32_t lB = pack_bf2(xv.z - __bfloat162float(h2), xv.w - __bfloat162float(h3));
            *(uint2*)(sm + QK_XH + c * XP + n * 2) = make_uint2(hA, hB);
            *(uint2*)(sm + QK_XL + c * XP + n * 2) = make_uint2(lA, lB);
        }
        // stage W chunks for all 3 weights
        #pragma unroll
        for (int w = 0; w < 3; ++w) {
            const float* W = Wp[w];
            #pragma unroll
            for (int r = 0; r < 4; ++r) {
                int idx = r * 256 + tid;
                int o = idx >> 4, f4 = idx & 15;
                int c = f4 * 4;
                float4 wv = *(const float4*)&W[(size_t)o * CIN + kc + c];
                __nv_bfloat16 h0 = __float2bfloat16_rn(wv.x);
                __nv_bfloat16 h1 = __float2bfloat16_rn(wv.y);
                __nv_bfloat16 h2 = __float2bfloat16_rn(wv.z);
                __nv_bfloat16 h3 = __float2bfloat16_rn(wv.w);
                uint32_t hA = ((uint32_t)*(uint16_t*)&h1 << 16) | *(uint16_t*)&h0;
                uint32_t hB = ((uint32_t)*(uint16_t*)&h3 << 16) | *(uint16_t*)&h2;
                uint32_t lA = pack_bf2(wv.x - __bfloat162float(h0), wv.y - __bfloat162float(h1));
                uint32_t lB = pack_bf2(wv.z - __bfloat162float(h2), wv.w - __bfloat162float(h3));
                *(uint2*)(sm + QK_W + w * 18432 + o * WP + c * 2) = make_uint2(hA, hB);
                *(uint2*)(sm + QK_W + w * 18432 + 9216 + o * WP + c * 2) = make_uint2(lA, lB);
            }
        }
        __syncthreads();

        // MMAs: x fragments loaded once per kt, reused for 3 weights
        #pragma unroll
        for (int kt = 0; kt < 4; ++kt) {
            uint32_t ah[4], al[4];
            LDSM4T(ah, aX + kt * 16 * XP);
            LDSM4T(al, aXl + kt * 16 * XP);
            #pragma unroll
            for (int w = 0; w < 3; ++w) {
                const uint32_t aW  = aW0 + w * 18432;
                const uint32_t aWl = aW + 9216;
                #pragma unroll
                for (int p = 0; p < 4; ++p) {
                    uint32_t bh[4], bl[4];
                    LDSM4(bh, aW + p * 16 * WP + kt * 32);
                    LDSM4(bl, aWl + p * 16 * WP + kt * 32);
                    float* d0 = d[w][2 * p];
                    float* d1 = d[w][2 * p + 1];
                    mma_bf16(d0, ah, bh[0], bh[1]);
                    mma_bf16(d1, ah, bh[2], bh[3]);
                    mma_bf16(d0, ah, bl[0], bl[1]);
                    mma_bf16(d1, ah, bl[2], bl[3]);
                    mma_bf16(d0, al, bh[0], bh[1]);
                    mma_bf16(d1, al, bh[2], bh[3]);
                }
            }
        }
    }

    // epilogue per weight
    #pragma unroll
    for (int w = 0; w < 3; ++w) {
        if (w < 2) {
            __nv_bfloat16* dh = (w == 0) ? g_ft_h : g_gt_h;
            __nv_bfloat16* dl = (w == 0) ? g_ft_l : g_gt_l;
            #pragma unroll
            for (int ot = 0; ot < 8; ++ot) {
                int o = ot * 8 + 2 * tg;
                int n_a = n0 + wid * 16 + g;
                size_t base_a = ((size_t)b * NN + n_a) * C8 + o;
                size_t base_b = base_a + 8 * C8;
                float v0 = d[w][ot][0], v1 = d[w][ot][1], v2 = d[w][ot][2], v3 = d[w][ot][3];
                __nv_bfloat16 h0 = __float2bfloat16_rn(v0);
                __nv_bfloat16 h1 = __float2bfloat16_rn(v1);
                __nv_bfloat16 h2 = __float2bfloat16_rn(v2);
                __nv_bfloat16 h3 = __float2bfloat16_rn(v3);
                *(uint32_t*)&dh[base_a] = ((uint32_t)*(uint16_t*)&h1 << 16) | *(uint16_t*)&h0;
                *(uint32_t*)&dh[base_b] = ((uint32_t)*(uint16_t*)&h3 << 16) | *(uint16_t*)&h2;
                *(uint32_t*)&dl[base_a] = pack_bf2(v0 - __bfloat162float(h0), v1 - __bfloat162float(h1));
                *(uint32_t*)&dl[base_b] = pack_bf2(v2 - __bfloat162float(h2), v3 - __bfloat162float(h3));
            }
        } else {
            #pragma unroll
            for (int ot = 0; ot < 8; ++ot) {
                int o = ot * 8 + 2 * tg;
                int n_a = n0 + wid * 16 + g;
                #pragma unroll
                for (int e = 0; e < 2; ++e) {
                    #pragma unroll
                    for (int rr = 0; rr < 2; ++rr) {
                        float v = d[w][ot][rr * 2 + e];
                        size_t idx = ((size_t)b * C8 + o + e) * NN + n_a + rr * 8;
                        __nv_bfloat16 h = __float2bfloat16_rn(v);
                        g_h_h[idx] = h;
                        g_h_l[idx] = __float2bfloat16_rn(v - __bfloat162float(h));
                    }
                }
            }
        }
    }
}

// ---------------------------------------------------------------------------
// Kernel 2: flash attention — movmatrix P-in-registers + 2-tile unroll.
// Q fragments loaded once per kt and shared across the 2 key tiles.
// 512 threads / 16 warps; 1 sync per 2 tiles.
// ---------------------------------------------------------------------------
#define AQ_PITCH 144
#define AT_QH 0
#define AT_QL 18432
#define AT_KV 36864            // + cbuf*73728 ; chunk = 2 tiles x 36864
                               // tile: KH 0, KL 9216, VH 18432, VL 27648
#define AT_OSM 0               // after loop: [4 wi][64 c][128 j] fp32
#define AT_RED 131072
#define AT_LINV 133120
#define SMEM_ATTN 184320

__global__ __launch_bounds__(512, 1) void attn_kernel() {
    extern __shared__ char sm[];
    const uint32_t sb = smem_u32(sm);
    const int tid = threadIdx.x, wid = tid >> 5, lane = tid & 31;
    const int g = lane >> 2, tg = lane & 3;
    const int wi = wid & 3, wj = wid >> 2;
    const int j0 = blockIdx.x * 128;
    const int b  = blockIdx.y;

    const uint4* kh_g = (const uint4*)(g_ft_h + (size_t)b * NN * C8);
    const uint4* kl_g = (const uint4*)(g_ft_l + (size_t)b * NN * C8);
    const uint4* vh_g = (const uint4*)(g_h_h + (size_t)b * C8 * NN);
    const uint4* vl_g = (const uint4*)(g_h_l + (size_t)b * C8 * NN);

    {   // stage Q tile (128 j x 64 c, hi/lo) — resident
        const uint4* qh = (const uint4*)(g_gt_h + ((size_t)b * NN + j0) * C8);
        const uint4* ql = (const uint4*)(g_gt_l + ((size_t)b * NN + j0) * C8);
        #pragma unroll
        for (int r = 0; r < 2; ++r) {
            int u = r * 512 + tid;
            int row = u >> 3, q = u & 7;
            *(uint4*)(sm + AT_QH + row * AQ_PITCH + q * 16) = qh[row * 8 + q];
            *(uint4*)(sm + AT_QL + row * AQ_PITCH + q * 16) = ql[row * 8 + q];
        }
    }

    const uint32_t offK = (wi * 16 + (lane & 15)) * AQ_PITCH + ((lane >> 4) & 1) * 16;
    const uint32_t offV0 = 18432 + (lane & 15) * AQ_PITCH + wi * 32 + ((lane >> 4) & 1) * 16;
    const uint32_t b_row = ((lane >> 4) & 1) * 8 + (lane & 7);
    const uint32_t b_cb  = ((lane >> 3) & 1) * 16;
    uint32_t aQ[2], aQl[2];
    #pragma unroll
    for (int ntp = 0; ntp < 2; ++ntp) {
        aQ[ntp]  = sb + AT_QH + (wj * 32 + ntp * 16 + b_row) * AQ_PITCH + b_cb;
        aQl[ntp] = aQ[ntp] + (AT_QL - AT_QH);
    }

    // stage one 2-tile chunk
    auto stage_chunk = [&](int it2, int cbuf) {
        const uint32_t cb = sb + AT_KV + cbuf * 73728;
        int row = tid >> 3, q = tid & 7;
        #pragma unroll
        for (int sub = 0; sub < 2; ++sub) {
            const int i0 = it2 * 128 + sub * 64;
            uint32_t drow = cb + sub * 36864 + row * AQ_PITCH + q * 16;
            CP_ASYNC16(drow, kh_g + (size_t)(i0 + row) * 8 + q);
            CP_ASYNC16(drow + 9216, kl_g + (size_t)(i0 + row) * 8 + q);
            size_t vsrc = (size_t)row * (NN / 8) + (i0 >> 3) + q;
            CP_ASYNC16(drow + 18432, vh_g + vsrc);
            CP_ASYNC16(drow + 27648, vl_g + vsrc);
        }
    };

    stage_chunk(0, 0);
    CP_COMMIT();

    float o[16][4] = {};
    float ls[8] = {};

    for (int it2 = 0; it2 < 32; ++it2) {
        const int cbuf = it2 & 1;
        const uint32_t cb = sb + AT_KV + cbuf * 73728;
        CP_WAIT0();
        __syncthreads();

        // ---- S for both tiles; Q fragments loaded once per kt ----
        float d[2][4][4] = {};
        #pragma unroll
        for (int kt = 0; kt < 4; ++kt) {
            uint32_t qh0[4], ql0[4], qh1[4], ql1[4];
            LDSM4(qh0, aQ[0] + kt * 32);
            LDSM4(ql0, aQl[0] + kt * 32);
            LDSM4(qh1, aQ[1] + kt * 32);
            LDSM4(ql1, aQl[1] + kt * 32);
            #pragma unroll
            for (int sub = 0; sub < 2; ++sub) {
                const uint32_t aK = cb + sub * 36864 + offK;
                uint32_t ah[4], al[4];
                LDSM4(ah, aK + kt * 32);
                LDSM4(al, aK + 9216 + kt * 32);
                float* d0 = d[sub][0];
                float* d1 = d[sub][1];
                float* d2 = d[sub][2];
                float* d3 = d[sub][3];
                mma_bf16(d0, ah, qh0[0], qh0[1]);
                mma_bf16(d1, ah, qh0[2], qh0[3]);
                mma_bf16(d2, ah, qh1[0], qh1[1]);
                mma_bf16(d3, ah, qh1[2], qh1[3]);
                mma_bf16(d0, ah, ql0[0], ql0[1]);
                mma_bf16(d1, ah, ql0[2], ql0[3]);
                mma_bf16(d2, ah, ql1[0], ql1[1]);
                mma_bf16(d3, ah, ql1[2], ql1[3]);
                mma_bf16(d0, al, qh0[0], qh0[1]);
                mma_bf16(d1, al, qh0[2], qh0[3]);
                mma_bf16(d2, al, qh1[0], qh1[1]);
                mma_bf16(d3, al, qh1[2], qh1[3]);
            }
        }

        if (it2 + 1 < 32) {
            stage_chunk(it2 + 1, cbuf ^ 1);
            CP_COMMIT();
        }

        // ---- per tile: exp -> movmatrix -> PV over own strip ----
        #pragma unroll
        for (int sub = 0; sub < 2; ++sub) {
            uint32_t pb[4][4];
            #pragma unroll
            for (int nt = 0; nt < 4; ++nt) {
                float e0 = fast_exp(d[sub][nt][0]);
                float e1 = fast_exp(d[sub][nt][1]);
                float e2 = fast_exp(d[sub][nt][2]);
                float e3 = fast_exp(d[sub][nt][3]);
                ls[nt * 2]     += e0 + e2;
                ls[nt * 2 + 1] += e1 + e3;
                __nv_bfloat162 hA = __floats2bfloat162_rn(e0, e1);
                __nv_bfloat162 hB = __floats2bfloat162_rn(e2, e3);
                uint32_t uhA, uhB; memcpy(&uhA, &hA, 4); memcpy(&uhB, &hB, 4);
                uint32_t ulA = pack_bf2(e0 - __bfloat162float(hA.x), e1 - __bfloat162float(hA.y));
                uint32_t ulB = pack_bf2(e2 - __bfloat162float(hB.x), e3 - __bfloat162float(hB.y));
                MOVMAT(pb[nt][0], uhA);
                MOVMAT(pb[nt][1], uhB);
                MOVMAT(pb[nt][2], ulA);
                MOVMAT(pb[nt][3], ulB);
            }
            #pragma unroll
            for (int ct = 0; ct < 4; ++ct) {
                uint32_t vh[4], vl[4];
                uint32_t aV = cb + sub * 36864 + offV0 + ct * (16 * AQ_PITCH);
                LDSM4(vh, aV);
                LDSM4(vl, aV + 9216);
                #pragma unroll
                for (int nt = 0; nt < 4; ++nt) {
                    float* oo = o[ct * 4 + nt];
                    mma_bf16(oo, vh, pb[nt][0], pb[nt][1]);
                    mma_bf16(oo, vh, pb[nt][2], pb[nt][3]);
                    mma_bf16(oo, vl, pb[nt][0], pb[nt][1]);
                }
            }
        }
    }

    __syncthreads();   // loop done; smem regions reusable

    float* Osm = (float*)(sm + AT_OSM);
    #pragma unroll
    for (int ct = 0; ct < 4; ++ct) {
        #pragma unroll
        for (int nt = 0; nt < 4; ++nt) {
            int c = ct * 16 + g;
            int jc = wj * 32 + nt * 8 + 2 * tg;
            float* os = Osm + ((size_t)wi * 64 + c) * 128 + jc;
            os[0] = o[ct * 4 + nt][0];
            os[1] = o[ct * 4 + nt][1];
            os[8 * 128] = o[ct * 4 + nt][2];
            os[8 * 128 + 1] = o[ct * 4 + nt][3];
        }
    }
    float* red = (float*)(sm + AT_RED);
    #pragma unroll
    for (int nt = 0; nt < 4; ++nt) {
        #pragma unroll
        for (int e = 0; e < 2; ++e) {
            float v = ls[nt * 2 + e];
            v += __shfl_down_sync(0xffffffffu, v, 4);
            v += __shfl_down_sync(0xffffffffu, v, 8);
            v += __shfl_down_sync(0xffffffffu, v, 16);
            if (lane < 4)
                red[wi * 128 + wj * 32 + nt * 8 + 2 * lane + e] = v;
        }
    }
    __syncthreads();

    float* linv = (float*)(sm + AT_LINV);
    if (tid < 128)
        linv[tid] = 1.0f / (red[tid] + red[128 + tid] + red[256 + tid] + red[384 + tid]);
    __syncthreads();

    {
        const int j = tid & 127;
        const int cg = tid >> 7;
        float inv = linv[j];
        float* ao = g_ao + (size_t)b * C8 * NN + j0 + j;
        #pragma unroll
        for (int k = 0; k < 16; ++k) {
            int c = cg * 16 + k;
            float v = Osm[(size_t)c * 128 + j]
                    + Osm[(size_t)(64 + c) * 128 + j]
                    + Osm[(size_t)(128 + c) * 128 + j]
                    + Osm[(size_t)(192 + c) * 128 + j];
            ao[(size_t)c * NN] = v * inv;
        }
    }
}

// ---------------------------------------------------------------------------
// Kernel 3: sa = Wv @ AO ; out = sa*gamma + x. UNCHANGED.
// ---------------------------------------------------------------------------
__global__ void proj_kernel(const float* __restrict__ x,
                            const float* __restrict__ Wv,
                            const float* __restrict__ gammap,
                            float* __restrict__ out) {
    __shared__ float Wvs[64 * 65];
    __shared__ float As[64 * 64];
    const int n0 = blockIdx.x * 64;
    const int m0 = blockIdx.y * 64;
    const int b  = blockIdx.z;
    const int tid = threadIdx.x;
    const int mg = tid >> 4, ng = tid & 15;

    {
        int idx = tid;
        #pragma unroll
        for (int r = 0; r < 16; ++r) {
            int m = idx >> 6, k = idx & 63;
            Wvs[m * 65 + k] = Wv[(size_t)(m0 + m) * C8 + k];
            idx += 256;
        }
    }
    {
        const float* A = g_ao + (size_t)b * C8 * NN;
        int idx = tid;
        #pragma unroll
        for (int r = 0; r < 16; ++r) {
            int k = idx >> 6, n = idx & 63;
            As[k * 64 + n] = A[(size_t)k * NN + n0 + n];
            idx += 256;
        }
    }
    __syncthreads();

    float acc[4][4] = {};
    #pragma unroll 8
    for (int k = 0; k < 64; ++k) {
        float a0 = Wvs[(mg * 4 + 0) * 65 + k];
        float a1 = Wvs[(mg * 4 + 1) * 65 + k];
        float a2 = Wvs[(mg * 4 + 2) * 65 + k];
        float a3 = Wvs[(mg * 4 + 3) * 65 + k];
        float4 bv = *(const float4*)&As[k * 64 + ng * 4];
        acc[0][0] = fmaf(a0, bv.x, acc[0][0]); acc[0][1] = fmaf(a0, bv.y, acc[0][1]);
        acc[0][2] = fmaf(a0, bv.z, acc[0][2]); acc[0][3] = fmaf(a0, bv.w, acc[0][3]);
        acc[1][0] = fmaf(a1, bv.x, acc[1][0]); acc[1][1] = fmaf(a1, bv.y, acc[1][1]);
        acc[1][2] = fmaf(a1, bv.z, acc[1][2]); acc[1][3] = fmaf(a1, bv.w, acc[1][3]);
        acc[2][0] = fmaf(a2, bv.x, acc[2][0]); acc[2][1] = fmaf(a2, bv.y, acc[2][1]);
        acc[2][2] = fmaf(a2, bv.z, acc[2][2]); acc[2][3] = fmaf(a2, bv.w, acc[2][3]);
        acc[3][0] = fmaf(a3, bv.x, acc[3][0]); acc[3][1] = fmaf(a3, bv.y, acc[3][1]);
        acc[3][2] = fmaf(a3, bv.z, acc[3][2]); acc[3][3] = fmaf(a3, bv.w, acc[3][3]);
    }

    const float gamma = gammap[0];
    float* outSA = out + (size_t)NB * CIN * NN;
    #pragma unroll
    for (int dm = 0; dm < 4; ++dm) {
        int m = m0 + mg * 4 + dm;
        size_t base = ((size_t)b * CIN + m) * NN + n0 + ng * 4;
        float4 sa = make_float4(acc[dm][0], acc[dm][1], acc[dm][2], acc[dm][3]);
        *(float4*)&outSA[base] = sa;
        float4 xv = *(const float4*)&x[base];
        float4 ov = make_float4(fmaf(sa.x, gamma, xv.x), fmaf(sa.y, gamma, xv.y),
                                fmaf(sa.z, gamma, xv.z), fmaf(sa.w, gamma, xv.w));
        *(float4*)&out[base] = ov;
    }
}

extern "C" void kernel_launch(void* const* d_in, const int* in_sizes, int n_in,
                              void* d_out, int out_size) {
    const float* x     = (const float*)d_in[0];
    const float* Wf    = (const float*)d_in[1];
    const float* Wg    = (const float*)d_in[2];
    const float* Wh    = (const float*)d_in[3];
    const float* Wv    = (const float*)d_in[4];
    const float* gamma = (const float*)d_in[5];
    float* out = (float*)d_out;

    cudaFuncSetAttribute(qkv_kernel,
                         cudaFuncAttributeMaxDynamicSharedMemorySize, SMEM_QKV);
    cudaFuncSetAttribute(attn_kernel,
                         cudaFuncAttributeMaxDynamicSharedMemorySize, SMEM_ATTN);

    qkv_kernel<<<dim3(32, 4), 256, SMEM_QKV>>>(x, Wf, Wg, Wh);
    attn_kernel<<<dim3(32, 4), 512, SMEM_ATTN>>>();
    proj_kernel<<<dim3(64, 8, 4), 256>>>(x, Wv, gamma, out);
}